// round 11
// baseline (speedup 1.0000x reference)
#include <cuda_runtime.h>
#include <cstddef>

#define N_NODES   50000
#define N_EDGES   800000
#define IN_CH     64
#define HIDDEN    128
#define NUM_GRAPHS 256

typedef unsigned long long u64;

// ---------------- scratch (static device globals; no allocation) ----------------
__device__ float g_agg1[(size_t)N_NODES * IN_CH];
__device__ float g_agg2[(size_t)N_NODES * HIDDEN];
__device__ float g_agg3[(size_t)N_NODES * HIDDEN];
__device__ float g_h1 [(size_t)N_NODES * HIDDEN];
__device__ float g_h2 [(size_t)N_NODES * HIDDEN];
__device__ float g_sums[(size_t)NUM_GRAPHS * HIDDEN];
// CSR-by-dst sort scratch
__device__ int   g_hist[N_NODES];
__device__ int   g_off [N_NODES + 1];
__device__ int   g_cursor[N_NODES];
__device__ int   g_src_sorted[N_EDGES];
__device__ float g_ea_sorted[(size_t)N_EDGES * 8];

// ---------------- packed f32x2 helpers (sm_103a FFMA2) ----------------
__device__ __forceinline__ u64 pack2(float lo, float hi) {
    u64 r;
    asm("mov.b64 %0, {%1, %2};" : "=l"(r) : "r"(__float_as_uint(lo)), "r"(__float_as_uint(hi)));
    return r;
}
__device__ __forceinline__ u64 fma2(u64 a, u64 b, u64 c) {
    u64 d;
    asm("fma.rn.f32x2 %0, %1, %2, %3;" : "=l"(d) : "l"(a), "l"(b), "l"(c));
    return d;
}
__device__ __forceinline__ float2 unpack2(u64 v) {
    unsigned lo, hi;
    asm("mov.b64 {%0, %1}, %2;" : "=r"(lo), "=r"(hi) : "l"(v));
    return make_float2(__uint_as_float(lo), __uint_as_float(hi));
}

// ---------------- vector reductions (sm_90+) ----------------
__device__ __forceinline__ void red_add_v4(float* addr, float4 v) {
    asm volatile("red.global.add.v4.f32 [%0], {%1,%2,%3,%4};"
                 :: "l"(addr), "f"(v.x), "f"(v.y), "f"(v.z), "f"(v.w) : "memory");
}

// ---------------- sort phase: CSR by dst ----------------
__global__ void zero_hist_kernel() {
    for (int i = blockIdx.x * blockDim.x + threadIdx.x; i < N_NODES; i += gridDim.x * blockDim.x)
        g_hist[i] = 0;
}
__global__ void hist_kernel(const int* __restrict__ ei) {
    const int* dstp = ei + N_EDGES;
    for (int e = blockIdx.x * blockDim.x + threadIdx.x; e < N_EDGES; e += gridDim.x * blockDim.x)
        atomicAdd(&g_hist[dstp[e]], 1);
}
__global__ void scan_kernel() {   // single block, 1024 threads
    __shared__ int part[1024];
    const int tid = threadIdx.x;
    const int CH = (N_NODES + 1023) / 1024;   // 49
    const int base = tid * CH;
    int s = 0;
    for (int i = 0; i < CH; i++) {
        int idx = base + i;
        if (idx < N_NODES) s += g_hist[idx];
    }
    part[tid] = s;
    __syncthreads();
    for (int d = 1; d < 1024; d <<= 1) {
        int v = (tid >= d) ? part[tid - d] : 0;
        __syncthreads();
        part[tid] += v;
        __syncthreads();
    }
    int run = (tid > 0) ? part[tid - 1] : 0;
    for (int i = 0; i < CH; i++) {
        int idx = base + i;
        if (idx < N_NODES) {
            int c = g_hist[idx];
            g_off[idx] = run;
            g_cursor[idx] = run;
            run += c;
        }
    }
    if (tid == 1023) g_off[N_NODES] = N_EDGES;
}
__global__ void scatter_kernel(const int* __restrict__ ei, const float* __restrict__ ea) {
    const int* srcp = ei;
    const int* dstp = ei + N_EDGES;
    const float4* ea4 = reinterpret_cast<const float4*>(ea);
    float4* eas4 = reinterpret_cast<float4*>(g_ea_sorted);
    for (int e = blockIdx.x * blockDim.x + threadIdx.x; e < N_EDGES; e += gridDim.x * blockDim.x) {
        const int d = dstp[e];
        const int pos = atomicAdd(&g_cursor[d], 1);
        g_src_sorted[pos] = srcp[e];
        eas4[(size_t)pos * 2]     = ea4[(size_t)e * 2];
        eas4[(size_t)pos * 2 + 1] = ea4[(size_t)e * 2 + 1];
    }
}

// ---------------- aggregation D=64: warp per node, float2 per lane, no atomics ----------------
__global__ __launch_bounds__(256, 4)
void agg_kernel64(const float* __restrict__ h,
                  const float* __restrict__ We,
                  const float* __restrict__ be,
                  float* __restrict__ agg) {
    __shared__ __align__(16) float2 Wes2[8 * 32];
    __shared__ __align__(16) float2 bes2[32];
    for (int i = threadIdx.x; i < 8 * 32; i += blockDim.x)
        Wes2[i] = reinterpret_cast<const float2*>(We)[i];
    if (threadIdx.x < 32) bes2[threadIdx.x] = reinterpret_cast<const float2*>(be)[threadIdx.x];
    __syncthreads();

    const int lane = threadIdx.x & 31;
    float2 w[8];
#pragma unroll
    for (int k = 0; k < 8; k++) w[k] = Wes2[k * 32 + lane];
    const float2 bj = bes2[lane];

    const int wid = (blockIdx.x * blockDim.x + threadIdx.x) >> 5;
    const int nw  = (gridDim.x * blockDim.x) >> 5;
    const int per = (N_NODES + nw - 1) / nw;
    const int n0  = wid * per;
    const int n1  = (n0 + per < N_NODES) ? (n0 + per) : N_NODES;

    const float2* h2v = reinterpret_cast<const float2*>(h);
    const float4* eas4 = reinterpret_cast<const float4*>(g_ea_sorted);

    for (int n = n0; n < n1; ++n) {
        const int start = g_off[n], end = g_off[n + 1];
        float2 acc = make_float2(0.f, 0.f);
        for (int e = start; e < end; ++e) {
            const int s = g_src_sorted[e];
            const float2 xv = h2v[(size_t)s * 32 + lane];
            const float4 a0 = eas4[(size_t)e * 2];
            const float4 a1 = eas4[(size_t)e * 2 + 1];
            float ak[8] = {a0.x, a0.y, a0.z, a0.w, a1.x, a1.y, a1.z, a1.w};
            float2 t = bj;
#pragma unroll
            for (int k = 0; k < 8; k++) {
                t.x = fmaf(ak[k], w[k].x, t.x);
                t.y = fmaf(ak[k], w[k].y, t.y);
            }
            acc.x += fmaxf(xv.x + t.x, 0.f);
            acc.y += fmaxf(xv.y + t.y, 0.f);
        }
        const float2 hv = h2v[(size_t)n * 32 + lane];
        reinterpret_cast<float2*>(agg)[(size_t)n * 32 + lane] =
            make_float2(hv.x + acc.x, hv.y + acc.y);
    }
}

// ---------------- aggregation D=128: warp per node, float4 per lane, no atomics ----------------
__global__ __launch_bounds__(256, 4)
void agg_kernel128(const float* __restrict__ h,
                   const float* __restrict__ We,
                   const float* __restrict__ be,
                   float* __restrict__ agg) {
    __shared__ __align__(16) float4 Wes4[8 * 32];
    __shared__ __align__(16) float4 bes4[32];
    for (int i = threadIdx.x; i < 8 * 32; i += blockDim.x)
        Wes4[i] = reinterpret_cast<const float4*>(We)[i];
    if (threadIdx.x < 32) bes4[threadIdx.x] = reinterpret_cast<const float4*>(be)[threadIdx.x];
    __syncthreads();

    const int lane = threadIdx.x & 31;
    float4 w[8];
#pragma unroll
    for (int k = 0; k < 8; k++) w[k] = Wes4[k * 32 + lane];
    const float4 bj = bes4[lane];

    const int wid = (blockIdx.x * blockDim.x + threadIdx.x) >> 5;
    const int nw  = (gridDim.x * blockDim.x) >> 5;
    const int per = (N_NODES + nw - 1) / nw;
    const int n0  = wid * per;
    const int n1  = (n0 + per < N_NODES) ? (n0 + per) : N_NODES;

    const float4* h4 = reinterpret_cast<const float4*>(h);
    const float4* eas4 = reinterpret_cast<const float4*>(g_ea_sorted);

    for (int n = n0; n < n1; ++n) {
        const int start = g_off[n], end = g_off[n + 1];
        float4 acc = make_float4(0.f, 0.f, 0.f, 0.f);
        for (int e = start; e < end; ++e) {
            const int s = g_src_sorted[e];
            const float4 xv = h4[(size_t)s * 32 + lane];
            const float4 a0 = eas4[(size_t)e * 2];
            const float4 a1 = eas4[(size_t)e * 2 + 1];
            float ak[8] = {a0.x, a0.y, a0.z, a0.w, a1.x, a1.y, a1.z, a1.w};
            float4 t = bj;
#pragma unroll
            for (int k = 0; k < 8; k++) {
                t.x = fmaf(ak[k], w[k].x, t.x);
                t.y = fmaf(ak[k], w[k].y, t.y);
                t.z = fmaf(ak[k], w[k].z, t.z);
                t.w = fmaf(ak[k], w[k].w, t.w);
            }
            acc.x += fmaxf(xv.x + t.x, 0.f);
            acc.y += fmaxf(xv.y + t.y, 0.f);
            acc.z += fmaxf(xv.z + t.z, 0.f);
            acc.w += fmaxf(xv.w + t.w, 0.f);
        }
        const float4 hv = h4[(size_t)n * 32 + lane];
        reinterpret_cast<float4*>(agg)[(size_t)n * 32 + lane] =
            make_float4(hv.x + acc.x, hv.y + acc.y, hv.z + acc.z, hv.w + acc.w);
    }
}

// ---------------- persistent node kernel: y = relu(agg @ W + b) ----------------
template <int K, bool POOL>
__global__ void node_kernel(const float* __restrict__ agg,
                            const float* __restrict__ W,
                            const float* __restrict__ b,
                            const int* __restrict__ batch,
                            float* __restrict__ out,
                            int ntiles) {
    extern __shared__ __align__(16) float sm[];
    float* Ws  = sm;               // K * 128
    float* ins = sm + K * 128;     // 64 * K
    const int tid = threadIdx.x;
    constexpr int K4 = K / 4;

    const float4* W4 = reinterpret_cast<const float4*>(W);
    float4* Ws4 = reinterpret_cast<float4*>(Ws);
    for (int i = tid; i < K * 32; i += 256) Ws4[i] = W4[i];

    const int w = tid >> 5, lane = tid & 31;
    const float4 bj = reinterpret_cast<const float4*>(b)[lane];
    const u64 bp0 = pack2(bj.x, bj.y), bp1 = pack2(bj.z, bj.w);
    const float4* a4 = reinterpret_cast<const float4*>(agg);
    float4* in4 = reinterpret_cast<float4*>(ins);

    for (int tile = blockIdx.x; tile < ntiles; tile += gridDim.x) {
        const int base = tile * 64;
        __syncthreads();
        for (int i = tid; i < 64 * K4; i += 256) {
            const int r = i / K4, c = i % K4;
            const int n = base + r;
            in4[i] = (n < N_NODES) ? a4[(size_t)n * K4 + c] : make_float4(0.f, 0.f, 0.f, 0.f);
        }
        __syncthreads();

        u64 acc0[8], acc1[8];
#pragma unroll
        for (int m = 0; m < 8; m++) { acc0[m] = bp0; acc1[m] = bp1; }

        const float* inrow = ins + (w * 8) * K;
#pragma unroll 1
        for (int k = 0; k < K; k += 4) {
            const float4 wv0 = Ws4[(k + 0) * 32 + lane];
            const float4 wv1 = Ws4[(k + 1) * 32 + lane];
            const float4 wv2 = Ws4[(k + 2) * 32 + lane];
            const float4 wv3 = Ws4[(k + 3) * 32 + lane];
            const u64 w00 = pack2(wv0.x, wv0.y), w01 = pack2(wv0.z, wv0.w);
            const u64 w10 = pack2(wv1.x, wv1.y), w11 = pack2(wv1.z, wv1.w);
            const u64 w20 = pack2(wv2.x, wv2.y), w21 = pack2(wv2.z, wv2.w);
            const u64 w30 = pack2(wv3.x, wv3.y), w31 = pack2(wv3.z, wv3.w);
#pragma unroll
            for (int m = 0; m < 8; m++) {
                const float4 iv = *reinterpret_cast<const float4*>(inrow + m * K + k);
                u64 t;
                t = pack2(iv.x, iv.x);
                acc0[m] = fma2(t, w00, acc0[m]);
                acc1[m] = fma2(t, w01, acc1[m]);
                t = pack2(iv.y, iv.y);
                acc0[m] = fma2(t, w10, acc0[m]);
                acc1[m] = fma2(t, w11, acc1[m]);
                t = pack2(iv.z, iv.z);
                acc0[m] = fma2(t, w20, acc0[m]);
                acc1[m] = fma2(t, w21, acc1[m]);
                t = pack2(iv.w, iv.w);
                acc0[m] = fma2(t, w30, acc0[m]);
                acc1[m] = fma2(t, w31, acc1[m]);
            }
        }

#pragma unroll
        for (int m = 0; m < 8; m++) {
            const int n = base + w * 8 + m;
            if (n < N_NODES) {
                const float2 lo = unpack2(acc0[m]);
                const float2 hi = unpack2(acc1[m]);
                float4 r;
                r.x = fmaxf(lo.x, 0.f);
                r.y = fmaxf(lo.y, 0.f);
                r.z = fmaxf(hi.x, 0.f);
                r.w = fmaxf(hi.y, 0.f);
                if (POOL) {
                    const int g = batch[n];
                    red_add_v4(&g_sums[(size_t)g * HIDDEN + lane * 4], r);
                } else {
                    reinterpret_cast<float4*>(out)[(size_t)n * 32 + lane] = r;
                }
            }
        }
    }
}

// ---------------- pool zero + final divide ----------------
__global__ void zero_pool_kernel() {
    int i = blockIdx.x * blockDim.x + threadIdx.x;
    if (i < NUM_GRAPHS * HIDDEN / 4)
        reinterpret_cast<float4*>(g_sums)[i] = make_float4(0.f, 0.f, 0.f, 0.f);
}
__global__ void div_kernel(const int* __restrict__ batch, float* __restrict__ out) {
    const int g = blockIdx.x;
    const int j = threadIdx.x;
    int lo = 0, hi = N_NODES;
    while (lo < hi) { int mid = (lo + hi) >> 1; if (batch[mid] < g) lo = mid + 1; else hi = mid; }
    const int first = lo;
    lo = first; hi = N_NODES;
    while (lo < hi) { int mid = (lo + hi) >> 1; if (batch[mid] < g + 1) lo = mid + 1; else hi = mid; }
    const float c = fmaxf((float)(lo - first), 1.0f);
    out[g * HIDDEN + j] = g_sums[g * HIDDEN + j] / c;
}

// ---------------- launch ----------------
extern "C" void kernel_launch(void* const* d_in, const int* in_sizes, int n_in,
                              void* d_out, int out_size) {
    const float* x     = (const float*)d_in[0];
    const int*   ei    = (const int*)d_in[1];
    const float* ea    = (const float*)d_in[2];
    const int*   batch = (const int*)d_in[3];
    const float *W1 = (const float*)d_in[4],  *b1 = (const float*)d_in[5];
    const float *We1= (const float*)d_in[6],  *be1= (const float*)d_in[7];
    const float *W2 = (const float*)d_in[8],  *b2 = (const float*)d_in[9];
    const float *We2= (const float*)d_in[10], *be2= (const float*)d_in[11];
    const float *W3 = (const float*)d_in[12], *b3 = (const float*)d_in[13];
    const float *We3= (const float*)d_in[14], *be3= (const float*)d_in[15];
    float* out = (float*)d_out;

    void* p;
    cudaGetSymbolAddress(&p, g_agg1); float* agg1 = (float*)p;
    cudaGetSymbolAddress(&p, g_agg2); float* agg2 = (float*)p;
    cudaGetSymbolAddress(&p, g_agg3); float* agg3 = (float*)p;
    cudaGetSymbolAddress(&p, g_h1);   float* h1   = (float*)p;
    cudaGetSymbolAddress(&p, g_h2);   float* h2   = (float*)p;

    const int smem64  = (64  * 128 + 64 * 64)  * 4;  // 48 KB
    const int smem128 = (128 * 128 + 64 * 128) * 4;  // 96 KB
    cudaFuncSetAttribute(node_kernel<64,  false>, cudaFuncAttributeMaxDynamicSharedMemorySize, smem64);
    cudaFuncSetAttribute(node_kernel<128, false>, cudaFuncAttributeMaxDynamicSharedMemorySize, smem128);
    cudaFuncSetAttribute(node_kernel<128, true >, cudaFuncAttributeMaxDynamicSharedMemorySize, smem128);

    const int AGG_GRID = 152 * 8;
    const int NTILES   = (N_NODES + 63) / 64;
    const int NGRID64  = 148 * 4;
    const int NGRID128 = 148 * 2;

    // ---- one-time sort (per launch): CSR by dst ----
    zero_hist_kernel<<<128, 256>>>();                                                   // 1
    hist_kernel<<<512, 256>>>(ei);                                                      // 2
    scan_kernel<<<1, 1024>>>();                                                         // 3
    scatter_kernel<<<512, 256>>>(ei, ea);                                               // 4

    // ---- layer 1 (64ch) ----
    agg_kernel64<<<AGG_GRID, 256>>>(x, We1, be1, agg1);                                 // 5
    node_kernel<64, false><<<NGRID64, 256, smem64>>>(agg1, W1, b1, nullptr, h1, NTILES);// 6
    // ---- layer 2 ----
    agg_kernel128<<<AGG_GRID, 256>>>(h1, We2, be2, agg2);                               // 7
    node_kernel<128, false><<<NGRID128, 256, smem128>>>(agg2, W2, b2, nullptr, h2, NTILES); // 8
    // ---- layer 3 + pool ----
    agg_kernel128<<<AGG_GRID, 256>>>(h2, We3, be3, agg3);                               // 9
    zero_pool_kernel<<<32, 256>>>();                                                    // 10
    node_kernel<128, true><<<NGRID128, 256, smem128>>>(agg3, W3, b3, batch, nullptr, NTILES); // 11
    div_kernel<<<NUM_GRAPHS, HIDDEN>>>(batch, out);                                     // 12
}